// round 1
// baseline (speedup 1.0000x reference)
#include <cuda_runtime.h>
#include <math.h>

// Problem constants
#define BB  4
#define TQ  1024
#define TKV 2048
#define DD  1024
#define HH  16
#define DHD 64

// GEMM tiling
#define BM 64
#define BN 64
#define BK 16

// Scratch (device globals; no allocations allowed)
__device__ float g_q[BB * TQ * DD];    // scaled q (scale^2 folded in)
__device__ float g_wv[BB * TQ * DD];   // attention output before Wo

// ---------------------------------------------------------------------------
// Copy the old (first TQ rows per batch) part of k/v cache into the output.
// dst linear index == src linear index for that region.
// ---------------------------------------------------------------------------
__global__ void copy_old_cache(const float4* __restrict__ ksrc,
                               const float4* __restrict__ vsrc,
                               float4* __restrict__ kdst,
                               float4* __restrict__ vdst) {
    int i = blockIdx.x * blockDim.x + threadIdx.x;   // over BB*TQ*DD/4 = 1M float4
    const int per_b = TQ * DD / 4;                    // 256K float4 per batch (old rows)
    const int total = BB * per_b;
    if (i >= total) return;
    int b = i / per_b;
    int rem = i - b * per_b;
    size_t idx = (size_t)b * (TKV * DD / 4) + rem;    // same offset in src and dst
    kdst[idx] = ksrc[idx];
    vdst[idx] = vsrc[idx];
}

// ---------------------------------------------------------------------------
// NT GEMM:  C[m,n] = sum_k A[m,k] * W[n,k]  (+ bias[n]),  M=4096, N=1024, K=1024
// mode 0: A=x, W=Wq, +bq, store (acc)*0.125 -> g_q            (scale^2 fold)
// mode 1: A=x, W=Wk,       store -> kout[b, TQ+t, n]
// mode 2: A=x, W=Wv, +bv,  store -> vout[b, TQ+t, n]
// mode 3: A=g_wv, W=Wo, +bo, store -> out[m, n]
// ---------------------------------------------------------------------------
__global__ __launch_bounds__(256) void gemm_nt(
    const float* __restrict__ X,
    const float* __restrict__ Wq, const float* __restrict__ bq,
    const float* __restrict__ Wk,
    const float* __restrict__ Wv, const float* __restrict__ bvv,
    const float* __restrict__ Wo, const float* __restrict__ bo,
    float* __restrict__ kout, float* __restrict__ vout,
    float* __restrict__ outp,
    int mode_base) {
    const int mode = mode_base + blockIdx.z;

    const float* A;
    const float* W;
    const float* bias;
    if (mode == 0)      { A = X;    W = Wq; bias = bq;  }
    else if (mode == 1) { A = X;    W = Wk; bias = 0;   }
    else if (mode == 2) { A = X;    W = Wv; bias = bvv; }
    else                { A = g_wv; W = Wo; bias = bo;  }

    __shared__ float As[BK][BM];
    __shared__ float Bs[BK][BN];

    const int tid = threadIdx.x;
    const int tx = tid & 15;       // N direction
    const int ty = tid >> 4;       // M direction
    const int m0 = blockIdx.y * BM;
    const int n0 = blockIdx.x * BN;

    const int lr  = tid >> 2;           // 0..63 tile row for loading
    const int lk4 = (tid & 3) << 2;     // k offset (float4)

    float acc[4][4];
#pragma unroll
    for (int i = 0; i < 4; i++)
#pragma unroll
        for (int j = 0; j < 4; j++) acc[i][j] = 0.f;

    for (int k0 = 0; k0 < DD; k0 += BK) {
        float4 av = *(const float4*)(A + (size_t)(m0 + lr) * DD + k0 + lk4);
        float4 bw = *(const float4*)(W + (size_t)(n0 + lr) * DD + k0 + lk4);
        As[lk4 + 0][lr] = av.x; As[lk4 + 1][lr] = av.y;
        As[lk4 + 2][lr] = av.z; As[lk4 + 3][lr] = av.w;
        Bs[lk4 + 0][lr] = bw.x; Bs[lk4 + 1][lr] = bw.y;
        Bs[lk4 + 2][lr] = bw.z; Bs[lk4 + 3][lr] = bw.w;
        __syncthreads();

#pragma unroll
        for (int kk = 0; kk < BK; kk++) {
            float4 a4 = *(const float4*)&As[kk][ty << 2];
            float4 b4 = *(const float4*)&Bs[kk][tx << 2];
            float ar[4] = {a4.x, a4.y, a4.z, a4.w};
            float br[4] = {b4.x, b4.y, b4.z, b4.w};
#pragma unroll
            for (int i = 0; i < 4; i++)
#pragma unroll
                for (int j = 0; j < 4; j++)
                    acc[i][j] = fmaf(ar[i], br[j], acc[i][j]);
        }
        __syncthreads();
    }

    // epilogue
#pragma unroll
    for (int i = 0; i < 4; i++) {
        int row = m0 + (ty << 2) + i;
#pragma unroll
        for (int j = 0; j < 4; j++) {
            int col = n0 + (tx << 2) + j;
            float v = acc[i][j];
            if (bias) v += bias[col];
            if (mode == 0) {
                g_q[(size_t)row * DD + col] = v * 0.125f;   // scale^2 = 1/sqrt(DH)
            } else if (mode == 3) {
                outp[(size_t)row * DD + col] = v;
            } else {
                int b = row >> 10;            // row / TQ
                int t = row & (TQ - 1);
                size_t di = (size_t)b * TKV * DD + (size_t)(TQ + t) * DD + col;
                if (mode == 1) kout[di] = v; else vout[di] = v;
            }
        }
    }
}

// ---------------------------------------------------------------------------
// Flash attention, fp32. One thread per query row; block = 128 queries of one
// (b, h). K/V tiles of 32 rows x 64 cols staged in smem, broadcast-read.
// ---------------------------------------------------------------------------
__global__ __launch_bounds__(128) void attn_kernel(
    const float* __restrict__ kc,    // [B, TKV, D] (final cache, in d_out)
    const float* __restrict__ vc,
    const float* __restrict__ mask)  // [TQ, TKV]
{
    __shared__ float4 Ks[32][16];
    __shared__ float4 Vs[32][16];

    const int tid = threadIdx.x;
    const int h = blockIdx.y;
    const int b = blockIdx.z;
    const int qrow = blockIdx.x * 128 + tid;     // 0..TQ-1

    const float* qptr = g_q + ((size_t)(b * TQ + qrow)) * DD + h * DHD;
    float4 qv[16];
#pragma unroll
    for (int c = 0; c < 16; c++) qv[c] = ((const float4*)qptr)[c];

    float4 o[16];
#pragma unroll
    for (int c = 0; c < 16; c++) o[c] = make_float4(0.f, 0.f, 0.f, 0.f);
    float m_run = -INFINITY, l_run = 0.f;

    const float* kb = kc + (size_t)b * TKV * DD + h * DHD;
    const float* vb = vc + (size_t)b * TKV * DD + h * DHD;
    const float* mrow = mask + (size_t)qrow * TKV;

    for (int kv0 = 0; kv0 < TKV; kv0 += 32) {
        __syncthreads();
#pragma unroll
        for (int it = 0; it < 4; it++) {
            int idx = tid + it * 128;            // 0..511
            int r = idx >> 4, c = idx & 15;
            Ks[r][c] = *(const float4*)(kb + (size_t)(kv0 + r) * DD + (c << 2));
            Vs[r][c] = *(const float4*)(vb + (size_t)(kv0 + r) * DD + (c << 2));
        }
        __syncthreads();

        float sv[32];
        float tmax = -INFINITY;
#pragma unroll
        for (int r = 0; r < 32; r++) {
            float s = 0.f;
#pragma unroll
            for (int c = 0; c < 16; c++) {
                float4 k4 = Ks[r][c];
                s = fmaf(qv[c].x, k4.x, s);
                s = fmaf(qv[c].y, k4.y, s);
                s = fmaf(qv[c].z, k4.z, s);
                s = fmaf(qv[c].w, k4.w, s);
            }
            s += mrow[kv0 + r];
            sv[r] = s;
            tmax = fmaxf(tmax, s);
        }

        float mnew = fmaxf(m_run, tmax);
        float corr = __expf(m_run - mnew);
        l_run *= corr;
#pragma unroll
        for (int c = 0; c < 16; c++) {
            o[c].x *= corr; o[c].y *= corr; o[c].z *= corr; o[c].w *= corr;
        }
#pragma unroll
        for (int r = 0; r < 32; r++) {
            float p = __expf(sv[r] - mnew);
            l_run += p;
#pragma unroll
            for (int c = 0; c < 16; c++) {
                float4 v4 = Vs[r][c];
                o[c].x = fmaf(p, v4.x, o[c].x);
                o[c].y = fmaf(p, v4.y, o[c].y);
                o[c].z = fmaf(p, v4.z, o[c].z);
                o[c].w = fmaf(p, v4.w, o[c].w);
            }
        }
        m_run = mnew;
    }

    float inv = 1.f / l_run;
    float* optr = g_wv + ((size_t)(b * TQ + qrow)) * DD + h * DHD;
#pragma unroll
    for (int c = 0; c < 16; c++) {
        float4 v = o[c];
        v.x *= inv; v.y *= inv; v.z *= inv; v.w *= inv;
        ((float4*)optr)[c] = v;
    }
}

// ---------------------------------------------------------------------------
// Launch
// ---------------------------------------------------------------------------
extern "C" void kernel_launch(void* const* d_in, const int* in_sizes, int n_in,
                              void* d_out, int out_size) {
    const float* x       = (const float*)d_in[0];
    const float* k_cache = (const float*)d_in[1];
    const float* v_cache = (const float*)d_in[2];
    const float* mask    = (const float*)d_in[3];
    const float* Wq      = (const float*)d_in[4];
    const float* bq      = (const float*)d_in[5];
    const float* Wk      = (const float*)d_in[6];
    const float* Wv      = (const float*)d_in[7];
    const float* bv      = (const float*)d_in[8];
    const float* Wo      = (const float*)d_in[9];
    const float* bo      = (const float*)d_in[10];

    float* outp = (float*)d_out;                          // [B, TQ, D]
    float* kout = outp + (size_t)BB * TQ * DD;            // [B, TKV, D]
    float* vout = kout + (size_t)BB * TKV * DD;           // [B, TKV, D]

    // 1) copy old cache rows (identity offsets)
    {
        int n4 = BB * TQ * DD / 4;
        copy_old_cache<<<(n4 + 255) / 256, 256>>>(
            (const float4*)k_cache, (const float4*)v_cache,
            (float4*)kout, (float4*)vout);
    }

    // 2) fused QKV projections (q scaled by 1/8 into g_q; k/v appended to caches)
    gemm_nt<<<dim3(DD / BN, (BB * TQ) / BM, 3), 256>>>(
        x, Wq, bq, Wk, Wv, bv, Wo, bo, kout, vout, outp, 0);

    // 3) attention -> g_wv
    attn_kernel<<<dim3(TQ / 128, HH, BB), 128>>>(kout, vout, mask);

    // 4) output projection
    gemm_nt<<<dim3(DD / BN, (BB * TQ) / BM, 1), 256>>>(
        x, Wq, bq, Wk, Wv, bv, Wo, bo, kout, vout, outp, 3);
}